// round 6
// baseline (speedup 1.0000x reference)
#include <cuda_runtime.h>
#include <cuda_bf16.h>
#include <cstdint>

#define NROWS 16384
#define KDIM  16384
#define NCOLS 64
#define KC    64
#define NCHUNK (KDIM / KC)

// -------- device scratch --------
__device__ __align__(256) float   g_sup[(size_t)NROWS * NCOLS];
__device__ __align__(256) uint8_t g_b1[(size_t)NCOLS * KDIM];   // s1 plane (s8)
__device__ __align__(256) uint8_t g_b0[(size_t)NCOLS * KDIM];   // s0 plane (s8)

// -------- helpers --------
__device__ __forceinline__ uint32_t smem_u32(const void* p) {
    uint32_t a;
    asm("{ .reg .u64 t; cvta.to.shared.u64 t, %1; cvt.u32.u64 %0, t; }" : "=r"(a) : "l"(p));
    return a;
}
__device__ __forceinline__ uint32_t sw128(uint32_t off) { return off ^ ((off >> 3) & 0x70); }

__device__ __forceinline__ void sts128(uint32_t addr, uint32_t a, uint32_t b, uint32_t c, uint32_t d) {
    asm volatile("st.shared.v4.b32 [%0], {%1,%2,%3,%4};"
                 :: "r"(addr), "r"(a), "r"(b), "r"(c), "r"(d) : "memory");
}

#define LDSM4(r, addr) \
    asm volatile("ldmatrix.sync.aligned.m8n8.x4.shared.b16 {%0,%1,%2,%3}, [%4];" \
                 : "=r"((r)[0]), "=r"((r)[1]), "=r"((r)[2]), "=r"((r)[3]) : "r"(addr))

// int8 MMA m16n8k32, s32 accum
#define IMMA_US(d, a, b0_, b1_) \
    asm volatile("mma.sync.aligned.m16n8k32.row.col.s32.u8.s8.s32 " \
                 "{%0,%1,%2,%3}, {%4,%5,%6,%7}, {%8,%9}, {%0,%1,%2,%3};" \
                 : "+r"((d)[0]), "+r"((d)[1]), "+r"((d)[2]), "+r"((d)[3]) \
                 : "r"((a)[0]), "r"((a)[1]), "r"((a)[2]), "r"((a)[3]), \
                   "r"(b0_), "r"(b1_))
#define IMMA_SS(d, a, b0_, b1_) \
    asm volatile("mma.sync.aligned.m16n8k32.row.col.s32.s8.s8.s32 " \
                 "{%0,%1,%2,%3}, {%4,%5,%6,%7}, {%8,%9}, {%0,%1,%2,%3};" \
                 : "+r"((d)[0]), "+r"((d)[1]), "+r"((d)[2]), "+r"((d)[3]) \
                 : "r"((a)[0]), "r"((a)[1]), "r"((a)[2]), "r"((a)[3]), \
                   "r"(b0_), "r"(b1_))

// -------- prep: support = x @ W ; store fp32 + int8 split planes --------
__global__ __launch_bounds__(256) void gcn_prep(const float* __restrict__ x,
                                                const float* __restrict__ W) {
    int tid = threadIdx.x;
    int rg = tid >> 3, cg = tid & 7;          // 8 lanes share x rows (coalesce-ish)
    int row0 = blockIdx.x * 128 + rg * 4;     // k dimension of support^T
    int c0 = cg * 8;                          // n dimension
    float acc[4][8];
#pragma unroll
    for (int i = 0; i < 4; i++)
#pragma unroll
        for (int j = 0; j < 8; j++) acc[i][j] = 0.f;

    const float4* x4 = reinterpret_cast<const float4*>(x);
    const float4* W4 = reinterpret_cast<const float4*>(W);

    for (int k4 = 0; k4 < 64; k4++) {
        float4 xv[4];
#pragma unroll
        for (int i = 0; i < 4; i++) xv[i] = __ldg(&x4[(size_t)(row0 + i) * 64 + k4]);
#pragma unroll
        for (int j = 0; j < 4; j++) {
            float4 wa = __ldg(&W4[(k4 * 4 + j) * 16 + cg * 2]);
            float4 wb = __ldg(&W4[(k4 * 4 + j) * 16 + cg * 2 + 1]);
#pragma unroll
            for (int i = 0; i < 4; i++) {
                float xs = (j == 0) ? xv[i].x : (j == 1) ? xv[i].y : (j == 2) ? xv[i].z : xv[i].w;
                acc[i][0] = fmaf(xs, wa.x, acc[i][0]);
                acc[i][1] = fmaf(xs, wa.y, acc[i][1]);
                acc[i][2] = fmaf(xs, wa.z, acc[i][2]);
                acc[i][3] = fmaf(xs, wa.w, acc[i][3]);
                acc[i][4] = fmaf(xs, wb.x, acc[i][4]);
                acc[i][5] = fmaf(xs, wb.y, acc[i][5]);
                acc[i][6] = fmaf(xs, wb.z, acc[i][6]);
                acc[i][7] = fmaf(xs, wb.w, acc[i][7]);
            }
        }
    }
#pragma unroll
    for (int i = 0; i < 4; i++) {
        float* sp = g_sup + (size_t)(row0 + i) * NCOLS + c0;
        reinterpret_cast<float4*>(sp)[0] = make_float4(acc[i][0], acc[i][1], acc[i][2], acc[i][3]);
        reinterpret_cast<float4*>(sp)[1] = make_float4(acc[i][4], acc[i][5], acc[i][6], acc[i][7]);
    }
    // int8 split planes: s ~ fix/4096, fix = s1*256 + s0, s1=(fix+128)>>8 (s8), s0 (s8)
#pragma unroll
    for (int j = 0; j < 8; j++) {
        int n = c0 + j;
        uint32_t v1 = 0, v0 = 0;
#pragma unroll
        for (int i = 0; i < 4; i++) {
            float sv = fminf(fmaxf(acc[i][j], -7.8f), 7.8f);
            int fx = __float2int_rn(sv * 4096.f);
            v1 |= ((uint32_t)(((fx + 128) >> 8) & 255)) << (8 * i);
            v0 |= ((uint32_t)(fx & 255)) << (8 * i);
        }
        *reinterpret_cast<uint32_t*>(g_b1 + (size_t)n * KDIM + row0) = v1;
        *reinterpret_cast<uint32_t*>(g_b0 + (size_t)n * KDIM + row0) = v0;
    }
}

// -------- main: out = relu(adj @ support + support + b) --------
// 128 CTAs x 128 rows, 512 threads, warp grid 4m x 4n, warp tile 32x16.
// Stage: A tile 128x128B (a1|a0 halves) = 16KB ; B tile 64x128B (s1|s0) = 8KB.
#define STAGE_BYTES 24576
#define SMEM_MAIN   (1024 + 2 * STAGE_BYTES)

__device__ __forceinline__ void stage_A(uint32_t At, const float* f,
                                        uint32_t a1_sts, uint32_t a0_sts) {
    uint32_t fb[16];
#pragma unroll
    for (int i = 0; i < 16; i++)
        fb[i] = __float2uint_rn(fmaf(f[i], 65280.f, 128.f));
    uint32_t a1p[4], a0p[4];
#pragma unroll
    for (int q = 0; q < 4; q++) {
        uint32_t t01 = __byte_perm(fb[q * 4], fb[q * 4 + 1], 0x5410);
        uint32_t t23 = __byte_perm(fb[q * 4 + 2], fb[q * 4 + 3], 0x5410);
        a1p[q] = __byte_perm(t01, t23, 0x7531);                 // high bytes (u8)
        a0p[q] = __byte_perm(t01, t23, 0x6420) ^ 0x80808080u;   // low-128 (s8)
    }
    sts128(At + a1_sts, a1p[0], a1p[1], a1p[2], a1p[3]);
    sts128(At + a0_sts, a0p[0], a0p[1], a0p[2], a0p[3]);
}

__global__ __launch_bounds__(512, 1) void gcn_main(const float* __restrict__ adj,
                                                   const float* __restrict__ bias,
                                                   float* __restrict__ out) {
    extern __shared__ char dsm[];
    uint32_t tiles = (smem_u32(dsm) + 1023) & ~1023u;
    int tid = threadIdx.x;
    int wid = tid >> 5;
    int lane = tid & 31;
    int row0 = blockIdx.x * 128;
    int wm = wid & 3, wn = wid >> 2;

    // A loader: 128 rows x 4 segs of 16 floats
    int arow = tid >> 2, aseg = tid & 3;
    uint32_t a1_sts = sw128((uint32_t)arow * 128 + (uint32_t)aseg * 16);
    uint32_t a0_sts = sw128((uint32_t)arow * 128 + 64 + (uint32_t)aseg * 16);
    const float4* apbase = reinterpret_cast<const float4*>(
        adj + (size_t)(row0 + arow) * KDIM + aseg * 16);

    // B loader: 64 n-rows x 2 planes x 4 k-segs of 16B
    int bn = tid >> 3, bp = (tid >> 2) & 1, bq = tid & 3;
    const uint8_t* bsrc = (bp ? g_b0 : g_b1) + (size_t)bn * KDIM + bq * 16;
    uint32_t b_sts = sw128((uint32_t)bn * 128 + (uint32_t)bp * 64 + (uint32_t)bq * 16);

    // fragment lane mappings (byte offsets)
    uint32_t a_r = ((lane >> 3) & 1) * 8 + (lane & 7);
    uint32_t a_k = ((lane >> 4) & 1) * 16;
    uint32_t b_n = ((lane >> 4) & 1) * 8 + (lane & 7);
    uint32_t b_k = ((lane >> 3) & 1) * 16;
    uint32_t arowb[2];
#pragma unroll
    for (int mt = 0; mt < 2; mt++) arowb[mt] = (wm * 32 + mt * 16 + a_r) * 128;
    uint32_t brow = (wn * 16 + b_n) * 128;

    int acc1[2][2][4], acc2[2][2][4];
#pragma unroll
    for (int mt = 0; mt < 2; mt++)
#pragma unroll
        for (int nt = 0; nt < 2; nt++)
#pragma unroll
            for (int j = 0; j < 4; j++) { acc1[mt][nt][j] = 0; acc2[mt][nt][j] = 0; }

    // ---- prologue: stage chunk 0 ----
    {
        float av[16];
#pragma unroll
        for (int q = 0; q < 4; q++)
            reinterpret_cast<float4*>(av)[q] = apbase[q];
        uint4 bv = *reinterpret_cast<const uint4*>(bsrc);
        stage_A(tiles, av, a1_sts, a0_sts);
        sts128(tiles + 16384 + b_sts, bv.x, bv.y, bv.z, bv.w);
    }
    __syncthreads();

    // ---- main loop ----
#pragma unroll 1
    for (int c = 0; c < NCHUNK; ++c) {
        int st = c & 1;
        uint32_t At = tiles + st * STAGE_BYTES;
        uint32_t Bt = At + 16384;

        // prefetch chunk c+1 (A from HBM, B from L2)
        float av[16];
        uint4 bv;
        bool more = (c + 1 < NCHUNK);
        if (more) {
            const float4* ap = apbase + (size_t)(c + 1) * (KC / 4);
#pragma unroll
            for (int q = 0; q < 4; q++)
                reinterpret_cast<float4*>(av)[q] = ap[q];
            bv = *reinterpret_cast<const uint4*>(bsrc + (size_t)(c + 1) * KC);
        }

        // MMA over this chunk
#pragma unroll
        for (int ks = 0; ks < 2; ks++) {
            uint32_t a1f[2][4], a0f[2][4], b1f[4], b0f[4];
            uint32_t ko = (uint32_t)(ks * 32);
#pragma unroll
            for (int mt = 0; mt < 2; mt++) {
                LDSM4(a1f[mt], At + sw128(arowb[mt] + ko + a_k));
                LDSM4(a0f[mt], At + sw128(arowb[mt] + 64 + ko + a_k));
            }
            LDSM4(b1f, Bt + sw128(brow + ko + b_k));
            LDSM4(b0f, Bt + sw128(brow + 64 + ko + b_k));
#pragma unroll
            for (int mt = 0; mt < 2; mt++) {
#pragma unroll
                for (int nt = 0; nt < 2; nt++) {
                    IMMA_US(acc1[mt][nt], a1f[mt], b1f[nt * 2], b1f[nt * 2 + 1]);
                    IMMA_US(acc2[mt][nt], a1f[mt], b0f[nt * 2], b0f[nt * 2 + 1]);
                    IMMA_SS(acc2[mt][nt], a0f[mt], b1f[nt * 2], b1f[nt * 2 + 1]);
                }
            }
        }

        if (more) {
            uint32_t At2 = tiles + (st ^ 1) * STAGE_BYTES;
            stage_A(At2, av, a1_sts, a0_sts);
            sts128(At2 + 16384 + b_sts, bv.x, bv.y, bv.z, bv.w);
        }
        __syncthreads();
    }

    // ---- epilogue: out = relu(acc1*C1 + acc2*C2 + support + bias) ----
    const float C1 = 1.0f / 4080.0f;       // 65536/(65280*4096)
    const float C2 = 1.0f / 1044480.0f;    // 256/(65280*4096)
    int g = lane >> 2, t = lane & 3;
#pragma unroll
    for (int mt = 0; mt < 2; mt++) {
        int ra = row0 + wm * 32 + mt * 16 + g;
#pragma unroll
        for (int nt = 0; nt < 2; nt++) {
            int col = wn * 16 + nt * 8 + t * 2;
            float2 bb = *reinterpret_cast<const float2*>(bias + col);
            float2 s0 = *reinterpret_cast<const float2*>(g_sup + (size_t)ra * NCOLS + col);
            float2 s1 = *reinterpret_cast<const float2*>(g_sup + (size_t)(ra + 8) * NCOLS + col);
            float2 r0, r1;
            r0.x = fmaxf(fmaf((float)acc1[mt][nt][0], C1, fmaf((float)acc2[mt][nt][0], C2, s0.x + bb.x)), 0.f);
            r0.y = fmaxf(fmaf((float)acc1[mt][nt][1], C1, fmaf((float)acc2[mt][nt][1], C2, s0.y + bb.y)), 0.f);
            r1.x = fmaxf(fmaf((float)acc1[mt][nt][2], C1, fmaf((float)acc2[mt][nt][2], C2, s1.x + bb.x)), 0.f);
            r1.y = fmaxf(fmaf((float)acc1[mt][nt][3], C1, fmaf((float)acc2[mt][nt][3], C2, s1.y + bb.y)), 0.f);
            *reinterpret_cast<float2*>(out + (size_t)ra * NCOLS + col) = r0;
            *reinterpret_cast<float2*>(out + (size_t)(ra + 8) * NCOLS + col) = r1;
        }
    }
}

extern "C" void kernel_launch(void* const* d_in, const int* in_sizes, int n_in,
                              void* d_out, int out_size) {
    const float *x = nullptr, *adj = nullptr, *W = nullptr, *b = nullptr;
    for (int i = 0; i < n_in; i++) {
        long s = in_sizes[i];
        if (s == (long)NROWS * 256)        x   = (const float*)d_in[i];
        else if (s == (long)NROWS * NROWS) adj = (const float*)d_in[i];
        else if (s == 256L * NCOLS)        W   = (const float*)d_in[i];
        else if (s == (long)NCOLS)         b   = (const float*)d_in[i];
    }
    cudaFuncSetAttribute(gcn_main, cudaFuncAttributeMaxDynamicSharedMemorySize, SMEM_MAIN);
    gcn_prep<<<128, 256>>>(x, W);
    gcn_main<<<128, 512, SMEM_MAIN>>>(adj, b, (float*)d_out);
}

// round 7
// speedup vs baseline: 2.0673x; 2.0673x over previous
#include <cuda_runtime.h>
#include <cuda_fp16.h>
#include <cstdint>

#define NROWS 16384
#define KDIM  16384
#define NCOLS 64
#define KC    64
#define NCHUNK (KDIM / KC)

// -------- device scratch --------
__device__ __align__(256) float  g_sup[(size_t)NROWS * NCOLS];
__device__ __align__(256) __half g_bh[(size_t)NCOLS * KDIM];   // support^T hi (fp16)
__device__ __align__(256) __half g_bl[(size_t)NCOLS * KDIM];   // support^T lo (fp16)

// -------- helpers --------
__device__ __forceinline__ uint32_t smem_u32(const void* p) {
    uint32_t a;
    asm("{ .reg .u64 t; cvta.to.shared.u64 t, %1; cvt.u32.u64 %0, t; }" : "=r"(a) : "l"(p));
    return a;
}
__device__ __forceinline__ uint32_t sw128(uint32_t off) { return off ^ ((off >> 3) & 0x70); }

// pack two floats to fp16x2, a -> LOW half
__device__ __forceinline__ uint32_t pack2h(float a, float b) {
    uint32_t r;
    asm("cvt.rn.f16x2.f32 %0, %1, %2;" : "=r"(r) : "f"(b), "f"(a));
    return r;
}
__device__ __forceinline__ void sts128(uint32_t addr, uint32_t a, uint32_t b, uint32_t c, uint32_t d) {
    asm volatile("st.shared.v4.b32 [%0], {%1,%2,%3,%4};"
                 :: "r"(addr), "r"(a), "r"(b), "r"(c), "r"(d) : "memory");
}

#define LDSM4(r, addr) \
    asm volatile("ldmatrix.sync.aligned.m8n8.x4.shared.b16 {%0,%1,%2,%3}, [%4];" \
                 : "=r"((r)[0]), "=r"((r)[1]), "=r"((r)[2]), "=r"((r)[3]) : "r"(addr))

#define MMAH(d, a, b0_, b1_) \
    asm volatile("mma.sync.aligned.m16n8k16.row.col.f32.f16.f16.f32 " \
                 "{%0,%1,%2,%3}, {%4,%5,%6,%7}, {%8,%9}, {%0,%1,%2,%3};" \
                 : "+f"((d)[0]), "+f"((d)[1]), "+f"((d)[2]), "+f"((d)[3]) \
                 : "r"((a)[0]), "r"((a)[1]), "r"((a)[2]), "r"((a)[3]), \
                   "r"(b0_), "r"(b1_))

// -------- prep: support = x @ W ; store fp32 + fp16 hi/lo transposed planes --------
__global__ __launch_bounds__(256) void gcn_prep(const float* __restrict__ x,
                                                const float* __restrict__ W) {
    int tid = threadIdx.x;
    int rg = tid >> 3, cg = tid & 7;
    int row0 = blockIdx.x * 128 + rg * 4;   // k dim of support^T
    int c0 = cg * 8;                        // n dim
    float acc[4][8];
#pragma unroll
    for (int i = 0; i < 4; i++)
#pragma unroll
        for (int j = 0; j < 8; j++) acc[i][j] = 0.f;

    const float4* x4 = reinterpret_cast<const float4*>(x);
    const float4* W4 = reinterpret_cast<const float4*>(W);

    for (int k4 = 0; k4 < 64; k4++) {
        float4 xv[4];
#pragma unroll
        for (int i = 0; i < 4; i++) xv[i] = __ldg(&x4[(size_t)(row0 + i) * 64 + k4]);
#pragma unroll
        for (int j = 0; j < 4; j++) {
            float4 wa = __ldg(&W4[(k4 * 4 + j) * 16 + cg * 2]);
            float4 wb = __ldg(&W4[(k4 * 4 + j) * 16 + cg * 2 + 1]);
#pragma unroll
            for (int i = 0; i < 4; i++) {
                float xs = (j == 0) ? xv[i].x : (j == 1) ? xv[i].y : (j == 2) ? xv[i].z : xv[i].w;
                acc[i][0] = fmaf(xs, wa.x, acc[i][0]);
                acc[i][1] = fmaf(xs, wa.y, acc[i][1]);
                acc[i][2] = fmaf(xs, wa.z, acc[i][2]);
                acc[i][3] = fmaf(xs, wa.w, acc[i][3]);
                acc[i][4] = fmaf(xs, wb.x, acc[i][4]);
                acc[i][5] = fmaf(xs, wb.y, acc[i][5]);
                acc[i][6] = fmaf(xs, wb.z, acc[i][6]);
                acc[i][7] = fmaf(xs, wb.w, acc[i][7]);
            }
        }
    }
#pragma unroll
    for (int i = 0; i < 4; i++) {
        float* sp = g_sup + (size_t)(row0 + i) * NCOLS + c0;
        reinterpret_cast<float4*>(sp)[0] = make_float4(acc[i][0], acc[i][1], acc[i][2], acc[i][3]);
        reinterpret_cast<float4*>(sp)[1] = make_float4(acc[i][4], acc[i][5], acc[i][6], acc[i][7]);
    }
    // fp16 hi/lo planes of support^T
#pragma unroll
    for (int j = 0; j < 8; j++) {
        int n = c0 + j;
        float h0 = __half2float(__float2half_rn(acc[0][j]));
        float h1 = __half2float(__float2half_rn(acc[1][j]));
        float h2 = __half2float(__float2half_rn(acc[2][j]));
        float h3 = __half2float(__float2half_rn(acc[3][j]));
        uint32_t hv0 = pack2h(h0, h1), hv1 = pack2h(h2, h3);
        uint32_t lv0 = pack2h(acc[0][j] - h0, acc[1][j] - h1);
        uint32_t lv1 = pack2h(acc[2][j] - h2, acc[3][j] - h3);
        size_t off = (size_t)n * KDIM + row0;
        *reinterpret_cast<uint2*>(g_bh + off) = make_uint2(hv0, hv1);
        *reinterpret_cast<uint2*>(g_bl + off) = make_uint2(lv0, lv1);
    }
}

// -------- main: out = relu(adj @ support + support + b) --------
// 128 CTAs x 128 rows, 512 threads, warp grid 4m x 4n, warp tile 32x16.
// Stage: A 128x128B fp16 = 16KB | B_hi 8KB | B_lo 8KB
#define STAGE_BYTES 32768
#define SMEM_MAIN   (1024 + 2 * STAGE_BYTES)

__device__ __forceinline__ void stage_A(uint32_t At, const float* f,
                                        uint32_t s0, uint32_t s1) {
    uint32_t h[8];
#pragma unroll
    for (int q = 0; q < 8; q++) h[q] = pack2h(f[2 * q], f[2 * q + 1]);
    sts128(At + s0, h[0], h[1], h[2], h[3]);
    sts128(At + s1, h[4], h[5], h[6], h[7]);
}

__global__ __launch_bounds__(512, 1) void gcn_main(const float* __restrict__ adj,
                                                   const float* __restrict__ bias,
                                                   float* __restrict__ out) {
    extern __shared__ char dsm[];
    uint32_t tiles = (smem_u32(dsm) + 1023) & ~1023u;
    int tid = threadIdx.x;
    int wid = tid >> 5;
    int lane = tid & 31;
    int row0 = blockIdx.x * 128;
    int wm = wid & 3, wn = wid >> 2;

    // A loader: 128 rows x 4 segs of 16 floats -> 32B fp16
    int arow = tid >> 2, aseg = tid & 3;
    uint32_t a_s0 = sw128((uint32_t)arow * 128 + (uint32_t)aseg * 32);
    uint32_t a_s1 = sw128((uint32_t)arow * 128 + (uint32_t)aseg * 32 + 16);
    const float4* apbase = reinterpret_cast<const float4*>(
        adj + (size_t)(row0 + arow) * KDIM + aseg * 16);

    // B loader: 64 rows x 8 segs of 16B, both planes per thread
    int bn = tid >> 3, bq = tid & 7;
    size_t bbyte = ((size_t)bn * KDIM) * 2 + (size_t)bq * 16;
    uint32_t b_sts = sw128((uint32_t)bn * 128 + (uint32_t)bq * 16);

    // fragment lane mappings
    uint32_t a_r = ((lane >> 3) & 1) * 8 + (lane & 7);
    uint32_t a_k = ((lane >> 4) & 1) * 16;
    uint32_t b_n = ((lane >> 4) & 1) * 8 + (lane & 7);
    uint32_t b_k = ((lane >> 3) & 1) * 16;
    uint32_t arowb[2];
#pragma unroll
    for (int mt = 0; mt < 2; mt++) arowb[mt] = (wm * 32 + mt * 16 + a_r) * 128;
    uint32_t browb = (wn * 16 + b_n) * 128;

    float acc[2][2][4];
#pragma unroll
    for (int mt = 0; mt < 2; mt++)
#pragma unroll
        for (int nt = 0; nt < 2; nt++)
#pragma unroll
            for (int j = 0; j < 4; j++) acc[mt][nt][j] = 0.f;

    // ---- prologue: stage chunk 0 ----
    {
        float av[16];
#pragma unroll
        for (int q = 0; q < 4; q++)
            reinterpret_cast<float4*>(av)[q] = apbase[q];
        uint4 bh = *reinterpret_cast<const uint4*>(reinterpret_cast<const char*>(g_bh) + bbyte);
        uint4 bl = *reinterpret_cast<const uint4*>(reinterpret_cast<const char*>(g_bl) + bbyte);
        stage_A(tiles, av, a_s0, a_s1);
        sts128(tiles + 16384 + b_sts, bh.x, bh.y, bh.z, bh.w);
        sts128(tiles + 24576 + b_sts, bl.x, bl.y, bl.z, bl.w);
    }
    __syncthreads();

    // ---- main loop ----
#pragma unroll 1
    for (int c = 0; c < NCHUNK; ++c) {
        int st = c & 1;
        uint32_t At = tiles + st * STAGE_BYTES;
        uint32_t Bh = At + 16384;
        uint32_t Bl = At + 24576;

        // prefetch chunk c+1 (A from HBM, B from L2)
        float av[16];
        uint4 bhv, blv;
        bool more = (c + 1 < NCHUNK);
        if (more) {
            const float4* ap = apbase + (size_t)(c + 1) * (KC / 4);
#pragma unroll
            for (int q = 0; q < 4; q++)
                reinterpret_cast<float4*>(av)[q] = ap[q];
            bhv = *reinterpret_cast<const uint4*>(
                reinterpret_cast<const char*>(g_bh) + bbyte + (size_t)(c + 1) * KC * 2);
            blv = *reinterpret_cast<const uint4*>(
                reinterpret_cast<const char*>(g_bl) + bbyte + (size_t)(c + 1) * KC * 2);
        }

        // MMA over this chunk
#pragma unroll
        for (int ks = 0; ks < 4; ks++) {
            uint32_t ko = (uint32_t)(ks * 32);
            uint32_t af[2][4], bhf[4], blf[4];
#pragma unroll
            for (int mt = 0; mt < 2; mt++)
                LDSM4(af[mt], At + sw128(arowb[mt] + ko + a_k));
            LDSM4(bhf, Bh + sw128(browb + ko + b_k));
            LDSM4(blf, Bl + sw128(browb + ko + b_k));
#pragma unroll
            for (int mt = 0; mt < 2; mt++) {
#pragma unroll
                for (int nt = 0; nt < 2; nt++) {
                    MMAH(acc[mt][nt], af[mt], bhf[nt * 2], bhf[nt * 2 + 1]);
                    MMAH(acc[mt][nt], af[mt], blf[nt * 2], blf[nt * 2 + 1]);
                }
            }
        }

        if (more) {
            uint32_t At2 = tiles + (st ^ 1) * STAGE_BYTES;
            stage_A(At2, av, a_s0, a_s1);
            sts128(At2 + 16384 + b_sts, bhv.x, bhv.y, bhv.z, bhv.w);
            sts128(At2 + 24576 + b_sts, blv.x, blv.y, blv.z, blv.w);
        }
        __syncthreads();
    }

    // ---- epilogue: out = relu(acc + support + bias) ----
    int g = lane >> 2, t = lane & 3;
#pragma unroll
    for (int mt = 0; mt < 2; mt++) {
        int ra = row0 + wm * 32 + mt * 16 + g;
#pragma unroll
        for (int nt = 0; nt < 2; nt++) {
            int col = wn * 16 + nt * 8 + t * 2;
            float2 bb = *reinterpret_cast<const float2*>(bias + col);
            float2 s0 = *reinterpret_cast<const float2*>(g_sup + (size_t)ra * NCOLS + col);
            float2 s1 = *reinterpret_cast<const float2*>(g_sup + (size_t)(ra + 8) * NCOLS + col);
            float2 r0, r1;
            r0.x = fmaxf(acc[mt][nt][0] + s0.x + bb.x, 0.f);
            r0.y = fmaxf(acc[mt][nt][1] + s0.y + bb.y, 0.f);
            r1.x = fmaxf(acc[mt][nt][2] + s1.x + bb.x, 0.f);
            r1.y = fmaxf(acc[mt][nt][3] + s1.y + bb.y, 0.f);
            *reinterpret_cast<float2*>(out + (size_t)ra * NCOLS + col) = r0;
            *reinterpret_cast<float2*>(out + (size_t)(ra + 8) * NCOLS + col) = r1;
        }
    }
}

extern "C" void kernel_launch(void* const* d_in, const int* in_sizes, int n_in,
                              void* d_out, int out_size) {
    const float *x = nullptr, *adj = nullptr, *W = nullptr, *b = nullptr;
    for (int i = 0; i < n_in; i++) {
        long s = in_sizes[i];
        if (s == (long)NROWS * 256)        x   = (const float*)d_in[i];
        else if (s == (long)NROWS * NROWS) adj = (const float*)d_in[i];
        else if (s == 256L * NCOLS)        W   = (const float*)d_in[i];
        else if (s == (long)NCOLS)         b   = (const float*)d_in[i];
    }
    cudaFuncSetAttribute(gcn_main, cudaFuncAttributeMaxDynamicSharedMemorySize, SMEM_MAIN);
    gcn_prep<<<128, 256>>>(x, W);
    gcn_main<<<128, 512, SMEM_MAIN>>>(adj, b, (float*)d_out);
}

// round 8
// speedup vs baseline: 2.2642x; 1.0952x over previous
#include <cuda_runtime.h>
#include <cuda_fp16.h>
#include <cstdint>

#define NROWS 16384
#define KDIM  16384
#define NCOLS 64
#define KC    64
#define NCHUNK (KDIM / KC)

// -------- device scratch --------
__device__ __align__(256) float  g_sup[(size_t)NROWS * NCOLS];
__device__ __align__(256) __half g_bh[(size_t)NCOLS * KDIM];   // support^T (fp16)

// -------- helpers --------
__device__ __forceinline__ uint32_t smem_u32(const void* p) {
    uint32_t a;
    asm("{ .reg .u64 t; cvta.to.shared.u64 t, %1; cvt.u32.u64 %0, t; }" : "=r"(a) : "l"(p));
    return a;
}
__device__ __forceinline__ uint32_t sw128(uint32_t off) { return off ^ ((off >> 3) & 0x70); }

// pack two floats to fp16x2, a -> LOW half
__device__ __forceinline__ uint32_t pack2h(float a, float b) {
    uint32_t r;
    asm("cvt.rn.f16x2.f32 %0, %1, %2;" : "=r"(r) : "f"(b), "f"(a));
    return r;
}
__device__ __forceinline__ void sts128(uint32_t addr, uint32_t a, uint32_t b, uint32_t c, uint32_t d) {
    asm volatile("st.shared.v4.b32 [%0], {%1,%2,%3,%4};"
                 :: "r"(addr), "r"(a), "r"(b), "r"(c), "r"(d) : "memory");
}
__device__ __forceinline__ void lds128f(uint32_t addr, float* v) {
    asm volatile("ld.shared.v4.f32 {%0,%1,%2,%3}, [%4];"
                 : "=f"(v[0]), "=f"(v[1]), "=f"(v[2]), "=f"(v[3]) : "r"(addr));
}

#define LDSM4(r, addr) \
    asm volatile("ldmatrix.sync.aligned.m8n8.x4.shared.b16 {%0,%1,%2,%3}, [%4];" \
                 : "=r"((r)[0]), "=r"((r)[1]), "=r"((r)[2]), "=r"((r)[3]) : "r"(addr))

#define MMAH(d, a, b0_, b1_) \
    asm volatile("mma.sync.aligned.m16n8k16.row.col.f32.f16.f16.f32 " \
                 "{%0,%1,%2,%3}, {%4,%5,%6,%7}, {%8,%9}, {%0,%1,%2,%3};" \
                 : "+f"((d)[0]), "+f"((d)[1]), "+f"((d)[2]), "+f"((d)[3]) \
                 : "r"((a)[0]), "r"((a)[1]), "r"((a)[2]), "r"((a)[3]), \
                   "r"(b0_), "r"(b1_))

// -------- prep: support = x @ W ; store fp32 + fp16 transposed plane --------
__global__ __launch_bounds__(256) void gcn_prep(const float* __restrict__ x,
                                                const float* __restrict__ W) {
    int tid = threadIdx.x;
    int rg = tid >> 3, cg = tid & 7;
    int row0 = blockIdx.x * 128 + rg * 4;   // k dim of support^T
    int c0 = cg * 8;                        // n dim
    float acc[4][8];
#pragma unroll
    for (int i = 0; i < 4; i++)
#pragma unroll
        for (int j = 0; j < 8; j++) acc[i][j] = 0.f;

    const float4* x4 = reinterpret_cast<const float4*>(x);
    const float4* W4 = reinterpret_cast<const float4*>(W);

    for (int k4 = 0; k4 < 64; k4++) {
        float4 xv[4];
#pragma unroll
        for (int i = 0; i < 4; i++) xv[i] = __ldg(&x4[(size_t)(row0 + i) * 64 + k4]);
#pragma unroll
        for (int j = 0; j < 4; j++) {
            float4 wa = __ldg(&W4[(k4 * 4 + j) * 16 + cg * 2]);
            float4 wb = __ldg(&W4[(k4 * 4 + j) * 16 + cg * 2 + 1]);
#pragma unroll
            for (int i = 0; i < 4; i++) {
                float xs = (j == 0) ? xv[i].x : (j == 1) ? xv[i].y : (j == 2) ? xv[i].z : xv[i].w;
                acc[i][0] = fmaf(xs, wa.x, acc[i][0]);
                acc[i][1] = fmaf(xs, wa.y, acc[i][1]);
                acc[i][2] = fmaf(xs, wa.z, acc[i][2]);
                acc[i][3] = fmaf(xs, wa.w, acc[i][3]);
                acc[i][4] = fmaf(xs, wb.x, acc[i][4]);
                acc[i][5] = fmaf(xs, wb.y, acc[i][5]);
                acc[i][6] = fmaf(xs, wb.z, acc[i][6]);
                acc[i][7] = fmaf(xs, wb.w, acc[i][7]);
            }
        }
    }
#pragma unroll
    for (int i = 0; i < 4; i++) {
        float* sp = g_sup + (size_t)(row0 + i) * NCOLS + c0;
        reinterpret_cast<float4*>(sp)[0] = make_float4(acc[i][0], acc[i][1], acc[i][2], acc[i][3]);
        reinterpret_cast<float4*>(sp)[1] = make_float4(acc[i][4], acc[i][5], acc[i][6], acc[i][7]);
    }
#pragma unroll
    for (int j = 0; j < 8; j++) {
        int n = c0 + j;
        uint32_t hv0 = pack2h(acc[0][j], acc[1][j]);
        uint32_t hv1 = pack2h(acc[2][j], acc[3][j]);
        *reinterpret_cast<uint2*>(g_bh + (size_t)n * KDIM + row0) = make_uint2(hv0, hv1);
    }
}

// -------- main: out = relu(adj @ support + support + b) --------
// 128 CTAs x 128 rows, 512 threads, warp grid 4m x 2n x 2k; warp tile 32x32 on K/2.
// Stage: A 128x128B fp16 = 16KB | B 8KB
#define STAGE_BYTES 24576
#define SMEM_MAIN   (1024 + 2 * STAGE_BYTES)

__device__ __forceinline__ void stage_A(uint32_t At, const float* f,
                                        uint32_t s0, uint32_t s1) {
    uint32_t h[8];
#pragma unroll
    for (int q = 0; q < 8; q++) h[q] = pack2h(f[2 * q], f[2 * q + 1]);
    sts128(At + s0, h[0], h[1], h[2], h[3]);
    sts128(At + s1, h[4], h[5], h[6], h[7]);
}

__global__ __launch_bounds__(512, 1) void gcn_main(const float* __restrict__ adj,
                                                   const float* __restrict__ bias,
                                                   float* __restrict__ out) {
    extern __shared__ char dsm[];
    uint32_t tiles = (smem_u32(dsm) + 1023) & ~1023u;
    int tid = threadIdx.x;
    int wid = tid >> 5;
    int lane = tid & 31;
    int row0 = blockIdx.x * 128;
    int wm = wid & 3, wn = (wid >> 2) & 1, wk = wid >> 3;

    // A loader: 128 rows x 4 segs of 16 floats -> 32B fp16
    int arow = tid >> 2, aseg = tid & 3;
    uint32_t a_s0 = sw128((uint32_t)arow * 128 + (uint32_t)aseg * 32);
    uint32_t a_s1 = sw128((uint32_t)arow * 128 + (uint32_t)aseg * 32 + 16);
    const float4* apbase = reinterpret_cast<const float4*>(
        adj + (size_t)(row0 + arow) * KDIM + aseg * 16);

    // B loader: 64 rows x 8 segs of 16B
    int bn = tid >> 3, bq = tid & 7;
    size_t bbyte = ((size_t)bn * KDIM) * 2 + (size_t)bq * 16;
    uint32_t b_sts = sw128((uint32_t)bn * 128 + (uint32_t)bq * 16);

    // fragment lane mappings
    uint32_t a_r = ((lane >> 3) & 1) * 8 + (lane & 7);
    uint32_t a_k = ((lane >> 4) & 1) * 16;
    uint32_t b_n = ((lane >> 4) & 1) * 8 + (lane & 7);
    uint32_t b_k = ((lane >> 3) & 1) * 16;
    uint32_t arowb[2], browb[2];
#pragma unroll
    for (int mt = 0; mt < 2; mt++) arowb[mt] = (wm * 32 + mt * 16 + a_r) * 128;
#pragma unroll
    for (int p = 0; p < 2; p++)   browb[p]  = (wn * 32 + p * 16 + b_n) * 128;

    float acc[2][4][4];
#pragma unroll
    for (int mt = 0; mt < 2; mt++)
#pragma unroll
        for (int nt = 0; nt < 4; nt++)
#pragma unroll
            for (int j = 0; j < 4; j++) acc[mt][nt][j] = 0.f;

    // ---- prologue: stage chunk 0 ----
    {
        float av[16];
#pragma unroll
        for (int q = 0; q < 4; q++)
            reinterpret_cast<float4*>(av)[q] = apbase[q];
        uint4 bv = *reinterpret_cast<const uint4*>(reinterpret_cast<const char*>(g_bh) + bbyte);
        stage_A(tiles, av, a_s0, a_s1);
        sts128(tiles + 16384 + b_sts, bv.x, bv.y, bv.z, bv.w);
    }
    __syncthreads();

    // ---- main loop ----
#pragma unroll 1
    for (int c = 0; c < NCHUNK; ++c) {
        int st = c & 1;
        uint32_t At = tiles + st * STAGE_BYTES;
        uint32_t Bt = At + 16384;

        // prefetch chunk c+1 (A from HBM, B from L2)
        float av[16];
        uint4 bv;
        bool more = (c + 1 < NCHUNK);
        if (more) {
            const float4* ap = apbase + (size_t)(c + 1) * (KC / 4);
#pragma unroll
            for (int q = 0; q < 4; q++)
                reinterpret_cast<float4*>(av)[q] = ap[q];
            bv = *reinterpret_cast<const uint4*>(
                reinterpret_cast<const char*>(g_bh) + bbyte + (size_t)(c + 1) * KC * 2);
        }

        // MMA over this chunk's k-half (wk selects 32 of 64)
#pragma unroll
        for (int ks = 0; ks < 2; ks++) {
            uint32_t ko = (uint32_t)wk * 64 + (uint32_t)(ks * 32);
            uint32_t af[2][4], bf[2][4];
#pragma unroll
            for (int mt = 0; mt < 2; mt++)
                LDSM4(af[mt], At + sw128(arowb[mt] + ko + a_k));
#pragma unroll
            for (int p = 0; p < 2; p++)
                LDSM4(bf[p], Bt + sw128(browb[p] + ko + b_k));
#pragma unroll
            for (int mt = 0; mt < 2; mt++) {
#pragma unroll
                for (int nt = 0; nt < 4; nt++) {
                    int p = nt >> 1, h = (nt & 1) * 2;
                    MMAH(acc[mt][nt], af[mt], bf[p][h], bf[p][h + 1]);
                }
            }
        }

        if (more) {
            uint32_t At2 = tiles + (st ^ 1) * STAGE_BYTES;
            stage_A(At2, av, a_s0, a_s1);
            sts128(At2 + 16384 + b_sts, bv.x, bv.y, bv.z, bv.w);
        }
        __syncthreads();
    }

    // ---- merge k-split partials: wk=1 warps dump accs to smem ----
    if (wk == 1) {
#pragma unroll
        for (int mt = 0; mt < 2; mt++)
#pragma unroll
            for (int nt = 0; nt < 4; nt++) {
                uint32_t off = tiles + (uint32_t)(wid & 7) * 4096 +
                               (uint32_t)(mt * 4 + nt) * 512 + (uint32_t)lane * 16;
                sts128(off, __float_as_uint(acc[mt][nt][0]), __float_as_uint(acc[mt][nt][1]),
                             __float_as_uint(acc[mt][nt][2]), __float_as_uint(acc[mt][nt][3]));
            }
    }
    __syncthreads();

    // ---- epilogue (wk=0 warps): out = relu(acc + partial + support + bias) ----
    if (wk == 0) {
        int g = lane >> 2, t = lane & 3;
#pragma unroll
        for (int mt = 0; mt < 2; mt++) {
            int ra = row0 + wm * 32 + mt * 16 + g;
#pragma unroll
            for (int nt = 0; nt < 4; nt++) {
                float p[4];
                lds128f(tiles + (uint32_t)wid * 4096 + (uint32_t)(mt * 4 + nt) * 512 +
                        (uint32_t)lane * 16, p);
                int col = wn * 32 + nt * 8 + t * 2;
                float2 bb = *reinterpret_cast<const float2*>(bias + col);
                float2 s0 = *reinterpret_cast<const float2*>(g_sup + (size_t)ra * NCOLS + col);
                float2 s1 = *reinterpret_cast<const float2*>(g_sup + (size_t)(ra + 8) * NCOLS + col);
                float2 r0, r1;
                r0.x = fmaxf(acc[mt][nt][0] + p[0] + s0.x + bb.x, 0.f);
                r0.y = fmaxf(acc[mt][nt][1] + p[1] + s0.y + bb.y, 0.f);
                r1.x = fmaxf(acc[mt][nt][2] + p[2] + s1.x + bb.x, 0.f);
                r1.y = fmaxf(acc[mt][nt][3] + p[3] + s1.y + bb.y, 0.f);
                *reinterpret_cast<float2*>(out + (size_t)ra * NCOLS + col) = r0;
                *reinterpret_cast<float2*>(out + (size_t)(ra + 8) * NCOLS + col) = r1;
            }
        }
    }
}

extern "C" void kernel_launch(void* const* d_in, const int* in_sizes, int n_in,
                              void* d_out, int out_size) {
    const float *x = nullptr, *adj = nullptr, *W = nullptr, *b = nullptr;
    for (int i = 0; i < n_in; i++) {
        long s = in_sizes[i];
        if (s == (long)NROWS * 256)        x   = (const float*)d_in[i];
        else if (s == (long)NROWS * NROWS) adj = (const float*)d_in[i];
        else if (s == 256L * NCOLS)        W   = (const float*)d_in[i];
        else if (s == (long)NCOLS)         b   = (const float*)d_in[i];
    }
    cudaFuncSetAttribute(gcn_main, cudaFuncAttributeMaxDynamicSharedMemorySize, SMEM_MAIN);
    gcn_prep<<<128, 256>>>(x, W);
    gcn_main<<<128, 512, SMEM_MAIN>>>(adj, b, (float*)d_out);
}

// round 10
// speedup vs baseline: 2.7366x; 1.2087x over previous
#include <cuda_runtime.h>
#include <cuda_fp16.h>
#include <cstdint>

#define NROWS 16384
#define KDIM  16384
#define NCOLS 64
#define KC    64
#define NCHUNK (KDIM / KC)
#define BSTRIDE ((KC * 2) / 16)   // uint4s per chunk of one B row = 8

// -------- device scratch --------
__device__ __align__(256) float  g_sup[(size_t)NROWS * NCOLS];
__device__ __align__(256) __half g_bh[(size_t)NCOLS * KDIM];   // support^T (fp16)

// -------- helpers --------
__device__ __forceinline__ uint32_t smem_u32(const void* p) {
    uint32_t a;
    asm("{ .reg .u64 t; cvta.to.shared.u64 t, %1; cvt.u32.u64 %0, t; }" : "=r"(a) : "l"(p));
    return a;
}
__device__ __forceinline__ uint32_t sw128(uint32_t off) { return off ^ ((off >> 3) & 0x70); }

// pack two floats to fp16x2, a -> LOW half
__device__ __forceinline__ uint32_t pack2h(float a, float b) {
    uint32_t r;
    asm("cvt.rn.f16x2.f32 %0, %1, %2;" : "=r"(r) : "f"(b), "f"(a));
    return r;
}
__device__ __forceinline__ void sts128(uint32_t addr, uint32_t a, uint32_t b, uint32_t c, uint32_t d) {
    asm volatile("st.shared.v4.b32 [%0], {%1,%2,%3,%4};"
                 :: "r"(addr), "r"(a), "r"(b), "r"(c), "r"(d) : "memory");
}
__device__ __forceinline__ void lds128f(uint32_t addr, float* v) {
    asm volatile("ld.shared.v4.f32 {%0,%1,%2,%3}, [%4];"
                 : "=f"(v[0]), "=f"(v[1]), "=f"(v[2]), "=f"(v[3]) : "r"(addr));
}

#define LDSM4(r, addr) \
    asm volatile("ldmatrix.sync.aligned.m8n8.x4.shared.b16 {%0,%1,%2,%3}, [%4];" \
                 : "=r"((r)[0]), "=r"((r)[1]), "=r"((r)[2]), "=r"((r)[3]) : "r"(addr))

#define MMAH(d, a, b0_, b1_) \
    asm volatile("mma.sync.aligned.m16n8k16.row.col.f32.f16.f16.f32 " \
                 "{%0,%1,%2,%3}, {%4,%5,%6,%7}, {%8,%9}, {%0,%1,%2,%3};" \
                 : "+f"((d)[0]), "+f"((d)[1]), "+f"((d)[2]), "+f"((d)[3]) \
                 : "r"((a)[0]), "r"((a)[1]), "r"((a)[2]), "r"((a)[3]), \
                   "r"(b0_), "r"(b1_))

// -------- prep: support = x @ W ; store fp32 + fp16 transposed plane --------
__global__ __launch_bounds__(256) void gcn_prep(const float* __restrict__ x,
                                                const float* __restrict__ W) {
    int tid = threadIdx.x;
    int rg = tid >> 3, cg = tid & 7;
    int row0 = blockIdx.x * 128 + rg * 4;   // k dim of support^T
    int c0 = cg * 8;                        // n dim
    float acc[4][8];
#pragma unroll
    for (int i = 0; i < 4; i++)
#pragma unroll
        for (int j = 0; j < 8; j++) acc[i][j] = 0.f;

    const float4* x4 = reinterpret_cast<const float4*>(x);
    const float4* W4 = reinterpret_cast<const float4*>(W);

    for (int k4 = 0; k4 < 64; k4++) {
        float4 xv[4];
#pragma unroll
        for (int i = 0; i < 4; i++) xv[i] = __ldg(&x4[(size_t)(row0 + i) * 64 + k4]);
#pragma unroll
        for (int j = 0; j < 4; j++) {
            float4 wa = __ldg(&W4[(k4 * 4 + j) * 16 + cg * 2]);
            float4 wb = __ldg(&W4[(k4 * 4 + j) * 16 + cg * 2 + 1]);
#pragma unroll
            for (int i = 0; i < 4; i++) {
                float xs = (j == 0) ? xv[i].x : (j == 1) ? xv[i].y : (j == 2) ? xv[i].z : xv[i].w;
                acc[i][0] = fmaf(xs, wa.x, acc[i][0]);
                acc[i][1] = fmaf(xs, wa.y, acc[i][1]);
                acc[i][2] = fmaf(xs, wa.z, acc[i][2]);
                acc[i][3] = fmaf(xs, wa.w, acc[i][3]);
                acc[i][4] = fmaf(xs, wb.x, acc[i][4]);
                acc[i][5] = fmaf(xs, wb.y, acc[i][5]);
                acc[i][6] = fmaf(xs, wb.z, acc[i][6]);
                acc[i][7] = fmaf(xs, wb.w, acc[i][7]);
            }
        }
    }
#pragma unroll
    for (int i = 0; i < 4; i++) {
        float* sp = g_sup + (size_t)(row0 + i) * NCOLS + c0;
        reinterpret_cast<float4*>(sp)[0] = make_float4(acc[i][0], acc[i][1], acc[i][2], acc[i][3]);
        reinterpret_cast<float4*>(sp)[1] = make_float4(acc[i][4], acc[i][5], acc[i][6], acc[i][7]);
    }
#pragma unroll
    for (int j = 0; j < 8; j++) {
        int n = c0 + j;
        uint32_t hv0 = pack2h(acc[0][j], acc[1][j]);
        uint32_t hv1 = pack2h(acc[2][j], acc[3][j]);
        *reinterpret_cast<uint2*>(g_bh + (size_t)n * KDIM + row0) = make_uint2(hv0, hv1);
    }
}

// -------- main: out = relu(adj @ support + support + b) --------
// 128 CTAs x 128 rows, 512 threads, warp grid 4m x 2n x 2k; warp tile 32x32 on K/2.
// Stage: A 128x128B fp16 = 16KB | B 8KB. Register prefetch distance 2.
#define STAGE_BYTES 24576
#define SMEM_MAIN   (1024 + 2 * STAGE_BYTES)

__device__ __forceinline__ void stage_A(uint32_t At, const float* f,
                                        uint32_t s0, uint32_t s1) {
    uint32_t h[8];
#pragma unroll
    for (int q = 0; q < 8; q++) h[q] = pack2h(f[2 * q], f[2 * q + 1]);
    sts128(At + s0, h[0], h[1], h[2], h[3]);
    sts128(At + s1, h[4], h[5], h[6], h[7]);
}

__global__ __launch_bounds__(512, 1) void gcn_main(const float* __restrict__ adj,
                                                   const float* __restrict__ bias,
                                                   float* __restrict__ out) {
    extern __shared__ char dsm[];
    uint32_t tiles = (smem_u32(dsm) + 1023) & ~1023u;
    int tid = threadIdx.x;
    int wid = tid >> 5;
    int lane = tid & 31;
    int row0 = blockIdx.x * 128;
    int wm = wid & 3, wn = (wid >> 2) & 1, wk = wid >> 3;

    // A loader: 128 rows x 4 segs of 16 floats -> 32B fp16
    int arow = tid >> 2, aseg = tid & 3;
    uint32_t a_s0 = sw128((uint32_t)arow * 128 + (uint32_t)aseg * 32);
    uint32_t a_s1 = sw128((uint32_t)arow * 128 + (uint32_t)aseg * 32 + 16);
    const float4* apbase = reinterpret_cast<const float4*>(
        adj + (size_t)(row0 + arow) * KDIM + aseg * 16);

    // B loader: 64 rows x 8 segs of 16B
    int bn = tid >> 3, bq = tid & 7;
    const uint4* bpbase = reinterpret_cast<const uint4*>(
        reinterpret_cast<const char*>(g_bh) + ((size_t)bn * KDIM) * 2 + (size_t)bq * 16);
    uint32_t b_sts = sw128((uint32_t)bn * 128 + (uint32_t)bq * 16);

    // fragment lane mappings
    uint32_t a_r = ((lane >> 3) & 1) * 8 + (lane & 7);
    uint32_t a_k = ((lane >> 4) & 1) * 16;
    uint32_t b_n = ((lane >> 4) & 1) * 8 + (lane & 7);
    uint32_t b_k = ((lane >> 3) & 1) * 16;
    uint32_t arowb[2], browb[2];
#pragma unroll
    for (int mt = 0; mt < 2; mt++) arowb[mt] = (wm * 32 + mt * 16 + a_r) * 128;
#pragma unroll
    for (int p = 0; p < 2; p++)   browb[p]  = (wn * 32 + p * 16 + b_n) * 128;

    float acc[2][4][4];
#pragma unroll
    for (int mt = 0; mt < 2; mt++)
#pragma unroll
        for (int nt = 0; nt < 4; nt++)
#pragma unroll
            for (int j = 0; j < 4; j++) acc[mt][nt][j] = 0.f;

    uint32_t St0 = tiles, St1 = tiles + STAGE_BYTES;

    // MMA over one chunk's k-half from stage (At, Bt)
#define MMA_CHUNK(At, Bt) do { \
    _Pragma("unroll") \
    for (int ks = 0; ks < 2; ks++) { \
        uint32_t ko = (uint32_t)wk * 64 + (uint32_t)(ks * 32); \
        uint32_t af[2][4], bf[2][4]; \
        _Pragma("unroll") \
        for (int mt = 0; mt < 2; mt++) \
            LDSM4(af[mt], (At) + sw128(arowb[mt] + ko + a_k)); \
        _Pragma("unroll") \
        for (int p = 0; p < 2; p++) \
            LDSM4(bf[p], (Bt) + sw128(browb[p] + ko + b_k)); \
        _Pragma("unroll") \
        for (int mt = 0; mt < 2; mt++) { \
            _Pragma("unroll") \
            for (int nt = 0; nt < 4; nt++) { \
                int p = nt >> 1, h = (nt & 1) * 2; \
                MMAH(acc[mt][nt], af[mt], bf[p][h], bf[p][h + 1]); \
            } \
        } \
    } \
} while (0)

    float av0[16], av1[16];
    uint4 bv0, bv1;

    // ---- prologue ----
    {
        // chunk 0: load, stage into St0
#pragma unroll
        for (int q = 0; q < 4; q++)
            reinterpret_cast<float4*>(av0)[q] = __ldcs(&apbase[q]);
        bv0 = *bpbase;
        stage_A(St0, av0, a_s0, a_s1);
        sts128(St0 + 16384 + b_sts, bv0.x, bv0.y, bv0.z, bv0.w);
        // chunk 1: issue loads
#pragma unroll
        for (int q = 0; q < 4; q++)
            reinterpret_cast<float4*>(av1)[q] = __ldcs(&apbase[(size_t)(KC / 4) + q]);
        bv1 = bpbase[BSTRIDE];
    }
    __syncthreads();

    // ---- main loop (unrolled x2, prefetch distance 2) ----
#pragma unroll 1
    for (int c = 0; c < NCHUNK; c += 2) {
        // chunk c on St0
        if (c + 2 < NCHUNK) {
            const float4* ap = apbase + (size_t)(c + 2) * (KC / 4);
#pragma unroll
            for (int q = 0; q < 4; q++)
                reinterpret_cast<float4*>(av0)[q] = __ldcs(&ap[q]);
            bv0 = bpbase[(size_t)(c + 2) * BSTRIDE];
        }
        MMA_CHUNK(St0, St0 + 16384);
        // stage chunk c+1 into St1 (loaded >= 1 full iteration ago)
        stage_A(St1, av1, a_s0, a_s1);
        sts128(St1 + 16384 + b_sts, bv1.x, bv1.y, bv1.z, bv1.w);
        __syncthreads();

        // chunk c+1 on St1
        if (c + 3 < NCHUNK) {
            const float4* ap = apbase + (size_t)(c + 3) * (KC / 4);
#pragma unroll
            for (int q = 0; q < 4; q++)
                reinterpret_cast<float4*>(av1)[q] = __ldcs(&ap[q]);
            bv1 = bpbase[(size_t)(c + 3) * BSTRIDE];
        }
        MMA_CHUNK(St1, St1 + 16384);
        if (c + 2 < NCHUNK) {
            stage_A(St0, av0, a_s0, a_s1);
            sts128(St0 + 16384 + b_sts, bv0.x, bv0.y, bv0.z, bv0.w);
        }
        __syncthreads();
    }
#undef MMA_CHUNK

    // ---- merge k-split partials: wk=1 warps dump accs to smem ----
    if (wk == 1) {
#pragma unroll
        for (int mt = 0; mt < 2; mt++)
#pragma unroll
            for (int nt = 0; nt < 4; nt++) {
                uint32_t off = tiles + (uint32_t)(wid & 7) * 4096 +
                               (uint32_t)(mt * 4 + nt) * 512 + (uint32_t)lane * 16;
                sts128(off, __float_as_uint(acc[mt][nt][0]), __float_as_uint(acc[mt][nt][1]),
                             __float_as_uint(acc[mt][nt][2]), __float_as_uint(acc[mt][nt][3]));
            }
    }
    __syncthreads();

    // ---- epilogue (wk=0 warps): out = relu(acc + partial + support + bias) ----
    if (wk == 0) {
        int g = lane >> 2, t = lane & 3;
#pragma unroll
        for (int mt = 0; mt < 2; mt++) {
            int ra = row0 + wm * 32 + mt * 16 + g;
#pragma unroll
            for (int nt = 0; nt < 4; nt++) {
                float p[4];
                lds128f(tiles + (uint32_t)wid * 4096 + (uint32_t)(mt * 4 + nt) * 512 +
                        (uint32_t)lane * 16, p);
                int col = wn * 32 + nt * 8 + t * 2;
                float2 bb = *reinterpret_cast<const float2*>(bias + col);
                float2 s0 = *reinterpret_cast<const float2*>(g_sup + (size_t)ra * NCOLS + col);
                float2 s1 = *reinterpret_cast<const float2*>(g_sup + (size_t)(ra + 8) * NCOLS + col);
                float2 r0, r1;
                r0.x = fmaxf(acc[mt][nt][0] + p[0] + s0.x + bb.x, 0.f);
                r0.y = fmaxf(acc[mt][nt][1] + p[1] + s0.y + bb.y, 0.f);
                r1.x = fmaxf(acc[mt][nt][2] + p[2] + s1.x + bb.x, 0.f);
                r1.y = fmaxf(acc[mt][nt][3] + p[3] + s1.y + bb.y, 0.f);
                *reinterpret_cast<float2*>(out + (size_t)ra * NCOLS + col) = r0;
                *reinterpret_cast<float2*>(out + (size_t)(ra + 8) * NCOLS + col) = r1;
            }
        }
    }
}

extern "C" void kernel_launch(void* const* d_in, const int* in_sizes, int n_in,
                              void* d_out, int out_size) {
    const float *x = nullptr, *adj = nullptr, *W = nullptr, *b = nullptr;
    for (int i = 0; i < n_in; i++) {
        long s = in_sizes[i];
        if (s == (long)NROWS * 256)        x   = (const float*)d_in[i];
        else if (s == (long)NROWS * NROWS) adj = (const float*)d_in[i];
        else if (s == 256L * NCOLS)        W   = (const float*)d_in[i];
        else if (s == (long)NCOLS)         b   = (const float*)d_in[i];
    }
    cudaFuncSetAttribute(gcn_main, cudaFuncAttributeMaxDynamicSharedMemorySize, SMEM_MAIN);
    gcn_prep<<<128, 256>>>(x, W);
    gcn_main<<<128, 512, SMEM_MAIN>>>(adj, b, (float*)d_out);
}